// round 4
// baseline (speedup 1.0000x reference)
#include <cuda_runtime.h>
#include <math.h>

#define BATCH 32
#define SEQT  512
#define HID   512
#define G4    2048   // 4*HID

// out layout (fp32): out[B][T][2H] @0, h_n[2][B][H] @16777216, c_n @16809984
#define OUT_HN 16777216
#define OUT_CN 16809984

// ---------------------------------------------------------------------------
// Device globals (allocation-free scratch)
// ---------------------------------------------------------------------------
__device__ float g_gx[2][SEQT][BATCH][G4];       // x@W_ih^T + b_ih + b_hh
__device__ float g_hB[2][2][BATCH][HID];         // [parity][dir][batch][unit]
#define FLAG_STRIDE 32                            // one 128B line per flag
__device__ int   g_flags[2][64 * FLAG_STRIDE];

// ---------------------------------------------------------------------------
// Packed fp32x2 FMA (Blackwell FFMA2; only reachable via PTX)
// ---------------------------------------------------------------------------
__device__ __forceinline__ float2 f2fma(float2 a, float2 b, float2 c) {
    unsigned long long ra = *reinterpret_cast<unsigned long long*>(&a);
    unsigned long long rb = *reinterpret_cast<unsigned long long*>(&b);
    unsigned long long rc = *reinterpret_cast<unsigned long long*>(&c);
    unsigned long long rd;
    asm("fma.rn.f32x2 %0, %1, %2, %3;" : "=l"(rd) : "l"(ra), "l"(rb), "l"(rc));
    return *reinterpret_cast<float2*>(&rd);
}
__device__ __forceinline__ float2 f2(float x, float y) { return make_float2(x, y); }

__device__ __forceinline__ float sigf(float x) { return 1.0f / (1.0f + __expf(-x)); }
__device__ __forceinline__ float tanhx(float x) { return 2.0f / (1.0f + __expf(-2.0f * x)) - 1.0f; }

// ---------------------------------------------------------------------------
// Init: h0 -> g_hB[0] (layout [dir][b][j] matches h0), reset flags
// ---------------------------------------------------------------------------
__global__ void init_state_kernel(const float* __restrict__ h0) {
    int idx = blockIdx.x * blockDim.x + threadIdx.x;   // 0..32767
    ((float*)g_hB)[idx] = h0[idx];                     // parity 0: first 32K floats
    if (idx < 128) g_flags[idx >> 6][(idx & 63) * FLAG_STRIDE] = 0;
}

// ---------------------------------------------------------------------------
// Phase 1: gx = x @ W_ih^T + biases. BM=BN=64, BK=32, 256 thr, 4x4 microtile,
// k-pair FFMA2 (both operands natural along k, no duplication).
// ---------------------------------------------------------------------------
#define BM 64
#define BN 64
#define BK 32
#define AST 36   // row stride (floats) for A/W tiles: 144B, 16B-aligned

__global__ __launch_bounds__(256) void gemm_ih_kernel(
        const float* __restrict__ x,
        const float* __restrict__ w_f, const float* __restrict__ w_r,
        const float* __restrict__ bi_f, const float* __restrict__ bh_f,
        const float* __restrict__ bi_r, const float* __restrict__ bh_r) {
    const int dir = blockIdx.z;
    const float* __restrict__ w  = dir ? w_r  : w_f;
    const float* __restrict__ bi = dir ? bi_r : bi_f;
    const float* __restrict__ bh = dir ? bh_r : bh_f;

    const int rm0 = blockIdx.y * BM;   // rows over T*B (row = t*32+b)
    const int cn0 = blockIdx.x * BN;   // cols over 4H

    __shared__ __align__(16) float As[BM * AST];
    __shared__ __align__(16) float Ws[BN * AST];

    const int tid = threadIdx.x;
    const int tr = tid / 16;           // 0..15 row group
    const int tc = tid % 16;           // 0..15 col group

    const int l_row = tid >> 2;        // 0..63
    const int l_k1  = (tid & 3) << 2;  // 0,4,8,12
    const int l_k2  = l_k1 + 16;

    const int r  = rm0 + l_row;
    int       tt = r >> 5;
    const int bb = r & 31;
    if (dir) tt = (SEQT - 1) - tt;
    const float* a_ptr = x + ((size_t)bb * SEQT + tt) * HID;
    const float* w_ptr = w + (size_t)(cn0 + l_row) * HID;

    float2 acc[4][4];
#pragma unroll
    for (int i = 0; i < 4; i++)
#pragma unroll
        for (int j = 0; j < 4; j++) acc[i][j] = f2(0.f, 0.f);

    for (int k0 = 0; k0 < HID; k0 += BK) {
        float4 av1 = *(const float4*)(a_ptr + k0 + l_k1);
        float4 av2 = *(const float4*)(a_ptr + k0 + l_k2);
        float4 wv1 = *(const float4*)(w_ptr + k0 + l_k1);
        float4 wv2 = *(const float4*)(w_ptr + k0 + l_k2);
        __syncthreads();
        *(float4*)&As[l_row * AST + l_k1] = av1;
        *(float4*)&As[l_row * AST + l_k2] = av2;
        *(float4*)&Ws[l_row * AST + l_k1] = wv1;
        *(float4*)&Ws[l_row * AST + l_k2] = wv2;
        __syncthreads();
#pragma unroll
        for (int q = 0; q < BK; q += 4) {
            float4 a0 = *(const float4*)&As[(tr * 4 + 0) * AST + q];
            float4 a1 = *(const float4*)&As[(tr * 4 + 1) * AST + q];
            float4 a2 = *(const float4*)&As[(tr * 4 + 2) * AST + q];
            float4 a3 = *(const float4*)&As[(tr * 4 + 3) * AST + q];
            float4 w0 = *(const float4*)&Ws[(tc * 4 + 0) * AST + q];
            float4 w1 = *(const float4*)&Ws[(tc * 4 + 1) * AST + q];
            float4 w2 = *(const float4*)&Ws[(tc * 4 + 2) * AST + q];
            float4 w3 = *(const float4*)&Ws[(tc * 4 + 3) * AST + q];
#define P1_STEP(i, j, av, wv) \
            acc[i][j] = f2fma(f2(av.x, av.y), f2(wv.x, wv.y), acc[i][j]); \
            acc[i][j] = f2fma(f2(av.z, av.w), f2(wv.z, wv.w), acc[i][j]);
            P1_STEP(0, 0, a0, w0) P1_STEP(0, 1, a0, w1) P1_STEP(0, 2, a0, w2) P1_STEP(0, 3, a0, w3)
            P1_STEP(1, 0, a1, w0) P1_STEP(1, 1, a1, w1) P1_STEP(1, 2, a1, w2) P1_STEP(1, 3, a1, w3)
            P1_STEP(2, 0, a2, w0) P1_STEP(2, 1, a2, w1) P1_STEP(2, 2, a2, w2) P1_STEP(2, 3, a2, w3)
            P1_STEP(3, 0, a3, w0) P1_STEP(3, 1, a3, w1) P1_STEP(3, 2, a3, w2) P1_STEP(3, 3, a3, w3)
#undef P1_STEP
        }
    }

    float* gxp = &g_gx[dir][0][0][0];
    const int cc = cn0 + tc * 4;
    const float bsum0 = bi[cc + 0] + bh[cc + 0];
    const float bsum1 = bi[cc + 1] + bh[cc + 1];
    const float bsum2 = bi[cc + 2] + bh[cc + 2];
    const float bsum3 = bi[cc + 3] + bh[cc + 3];
#pragma unroll
    for (int i = 0; i < 4; i++) {
        const int rr = rm0 + tr * 4 + i;
        float4 o;
        o.x = acc[i][0].x + acc[i][0].y + bsum0;
        o.y = acc[i][1].x + acc[i][1].y + bsum1;
        o.z = acc[i][2].x + acc[i][2].y + bsum2;
        o.w = acc[i][3].x + acc[i][3].y + bsum3;
        *(float4*)(gxp + (size_t)rr * G4 + cc) = o;
    }
}

// ---------------------------------------------------------------------------
// Phase 2: persistent recurrence. 128 blocks (64/dir), 256 threads each.
// Per-block padded flags + nanosleep backoff. W slice [c][k] in smem for
// all steps; h staged [b][k]; k-pair FFMA2, no duplication.
// ---------------------------------------------------------------------------
#define NBLK_PER_DIR 64
#define JB 8
#define NC 32
#define HST 516   // k-row stride in floats (2064B, 16B-aligned, bank-skewed)

#define SM_WS 0                               // float Ws[32][516] = 66048 B
#define SM_HS 66048                           // float Hs[32][516] = 66048 B
#define SM_P  132096                          // float P[32][34]   =  4352 B
#define SM_HO 136448                          // float HO[32][8]   =  1024 B
#define SMEM_TOTAL (136448 + 1024)

__global__ __launch_bounds__(256, 1)
void lstm_persistent_kernel(const float* __restrict__ w_hh_f,
                            const float* __restrict__ w_hh_r,
                            const float* __restrict__ c0,
                            float* __restrict__ out) {
    extern __shared__ char smem_raw[];
    float* Ws = (float*)(smem_raw + SM_WS);
    float* Hs = (float*)(smem_raw + SM_HS);
    float* P  = (float*)(smem_raw + SM_P);    // row stride 34, [local_col][b]
    float* HO = (float*)(smem_raw + SM_HO);   // [b][8]

    const int tid = threadIdx.x;
    const int dir = blockIdx.x >> 6;
    const int blk = blockIdx.x & 63;
    const int j0  = blk * JB;
    const float* __restrict__ w = dir ? w_hh_r : w_hh_f;
    int* flags = &g_flags[dir][0];

    // ---- load W slice into [c][k] layout (once) ----
    {
        const int c   = tid >> 3;              // 0..31 local gate col
        const int seg = tid & 7;               // k segment of 64
        const int g = c >> 3, u = c & 7;
        const float* wrow = w + (size_t)(g * HID + j0 + u) * HID + seg * 64;
        float* wdst = Ws + c * HST + seg * 64;
#pragma unroll
        for (int q = 0; q < 16; q++)
            *(float4*)(wdst + q * 4) = *(const float4*)(wrow + q * 4);
    }

    // ---- pointwise ownership: thread -> (u = tid&7, b = tid>>3) ----
    const int pu = tid & 7;
    const int pb = tid >> 3;
    float creg = c0[((size_t)dir * BATCH + pb) * HID + j0 + pu];

    // ---- GEMM thread coords: 16 batch-pairs x 16 col-pairs ----
    const int tcg = tid & 15;
    const int tbg = tid >> 4;
    const int c0l = tcg * 2;
    const int b0  = tbg * 2;
    const int gcol0 = ((c0l)     >> 3) * HID + j0 + ((c0l)     & 7);
    const int gcol1 = ((c0l + 1) >> 3) * HID + j0 + ((c0l + 1) & 7);

    const float4* hB0 = (const float4*)&g_hB[0][dir][0][0];
    const float4* hB1 = (const float4*)&g_hB[1][dir][0][0];

    __syncthreads();

    for (int t = 0; t < SEQT; t++) {
        // prefetch gx (independent of h) — in flight during the wait
        const float* gxp = &g_gx[dir][t][0][0];
        float gx00 = gxp[(b0 + 0) * G4 + gcol0], gx01 = gxp[(b0 + 0) * G4 + gcol1];
        float gx10 = gxp[(b0 + 1) * G4 + gcol0], gx11 = gxp[(b0 + 1) * G4 + gcol1];

        // wait: lane i polls block i's private 128B flag line, with backoff
        if (t > 0 && tid < NBLK_PER_DIR) {
            int* fp = flags + tid * FLAG_STRIDE;
            int v;
            asm volatile("ld.acquire.gpu.s32 %0, [%1];" : "=r"(v) : "l"(fp));
            while (v < t) {
                __nanosleep(100);
                asm volatile("ld.acquire.gpu.s32 %0, [%1];" : "=r"(v) : "l"(fp));
            }
        }
        __syncthreads();

        // stage h: 64KB coalesced copy into Hs[b][k] (padded rows)
        {
            const float4* src = (t & 1) ? hB1 : hB0;
#pragma unroll
            for (int it = 0; it < 16; it++) {
                const int idx = it * 256 + tid;          // 0..4095
                const int b  = idx >> 7;
                const int kq = idx & 127;
                *(float4*)&Hs[b * HST + kq * 4] = src[idx];
            }
        }
        __syncthreads();

        // GEMM: C[b][c] = sum_k h[b][k]*W[c][k]; acc lanes = (k even, k odd)
        float2 a00 = f2(0.f, 0.f), a01 = f2(0.f, 0.f);
        float2 a10 = f2(0.f, 0.f), a11 = f2(0.f, 0.f);
        {
            const float* hp0 = Hs + b0 * HST;
            const float* hp1 = hp0 + HST;
            const float* wp0 = Ws + c0l * HST;
            const float* wp1 = wp0 + HST;
#pragma unroll 8
            for (int k = 0; k < HID; k += 4) {
                float4 ha = *(const float4*)(hp0 + k);
                float4 hb = *(const float4*)(hp1 + k);
                float4 wa = *(const float4*)(wp0 + k);
                float4 wb = *(const float4*)(wp1 + k);
                a00 = f2fma(f2(ha.x, ha.y), f2(wa.x, wa.y), a00);
                a00 = f2fma(f2(ha.z, ha.w), f2(wa.z, wa.w), a00);
                a01 = f2fma(f2(ha.x, ha.y), f2(wb.x, wb.y), a01);
                a01 = f2fma(f2(ha.z, ha.w), f2(wb.z, wb.w), a01);
                a10 = f2fma(f2(hb.x, hb.y), f2(wa.x, wa.y), a10);
                a10 = f2fma(f2(hb.z, hb.w), f2(wa.z, wa.w), a10);
                a11 = f2fma(f2(hb.x, hb.y), f2(wb.x, wb.y), a11);
                a11 = f2fma(f2(hb.z, hb.w), f2(wb.z, wb.w), a11);
            }
        }
        P[(c0l)     * 34 + b0]     = a00.x + a00.y + gx00;
        P[(c0l + 1) * 34 + b0]     = a01.x + a01.y + gx01;
        P[(c0l)     * 34 + b0 + 1] = a10.x + a10.y + gx10;
        P[(c0l + 1) * 34 + b0 + 1] = a11.x + a11.y + gx11;
        __syncthreads();

        // pointwise: 1 item per thread, cell state in register
        float* hdst = (t & 1) ? (float*)&g_hB[0][dir][0][0]
                              : (float*)&g_hB[1][dir][0][0];
        {
            float iv = sigf(P[(pu)      * 34 + pb]);
            float fv = sigf(P[(8 + pu)  * 34 + pb]);
            float gv = tanhx(P[(16 + pu) * 34 + pb]);
            float ov = sigf(P[(24 + pu) * 34 + pb]);
            creg = fv * creg + iv * gv;
            float hnew = ov * tanhx(creg);
            hdst[pb * HID + j0 + pu] = hnew;
            HO[pb * 8 + pu] = hnew;
            if (t == SEQT - 1) {
                out[OUT_HN + ((size_t)dir * BATCH + pb) * HID + j0 + pu] = hnew;
                out[OUT_CN + ((size_t)dir * BATCH + pb) * HID + j0 + pu] = creg;
            }
        }
        __syncthreads();   // hdst + HO visible block-wide

        // coalesced out write (128 threads x float2)
        if (tid < 128) {
            const int tout = dir ? (SEQT - 1 - t) : t;
            const int ob = tid >> 2;
            const int ou = (tid & 3) * 2;
            float2 v = *(const float2*)&HO[ob * 8 + ou];
            *(float2*)&out[((size_t)ob * SEQT + tout) * (2 * HID) + dir * HID + j0 + ou] = v;
        }

        // signal completion of step t (block's h stores ordered via the bar)
        if (tid == 0) {
            asm volatile("st.release.gpu.s32 [%0], %1;"
                         :: "l"(flags + blk * FLAG_STRIDE), "r"(t + 1));
        }
    }
}

// ---------------------------------------------------------------------------
// Launch
// ---------------------------------------------------------------------------
extern "C" void kernel_launch(void* const* d_in, const int* in_sizes, int n_in,
                              void* d_out, int out_size) {
    const float* x      = (const float*)d_in[0];
    const float* h0     = (const float*)d_in[1];
    const float* c0     = (const float*)d_in[2];
    const float* w_ih_f = (const float*)d_in[3];
    const float* w_hh_f = (const float*)d_in[4];
    const float* b_ih_f = (const float*)d_in[5];
    const float* b_hh_f = (const float*)d_in[6];
    const float* w_ih_r = (const float*)d_in[7];
    const float* w_hh_r = (const float*)d_in[8];
    const float* b_ih_r = (const float*)d_in[9];
    const float* b_hh_r = (const float*)d_in[10];
    float* out = (float*)d_out;

    cudaFuncSetAttribute(lstm_persistent_kernel,
                         cudaFuncAttributeMaxDynamicSharedMemorySize, SMEM_TOTAL);

    init_state_kernel<<<128, 256>>>(h0);

    dim3 ggrid(G4 / BN, (SEQT * BATCH) / BM, 2);
    gemm_ih_kernel<<<ggrid, 256>>>(x, w_ih_f, w_ih_r,
                                   b_ih_f, b_hh_f, b_ih_r, b_hh_r);

    lstm_persistent_kernel<<<2 * NBLK_PER_DIR, 256, SMEM_TOTAL>>>(
        w_hh_f, w_hh_r, c0, out);
}

// round 7
// speedup vs baseline: 1.5974x; 1.5974x over previous
#include <cuda_runtime.h>
#include <math.h>

#define BATCH 32
#define SEQT  512
#define HID   512
#define G4    2048   // 4*HID

// out layout (fp32): out[B][T][2H] @0, h_n[2][B][H] @16777216, c_n @16809984
#define OUT_HN 16777216
#define OUT_CN 16809984

// ---------------------------------------------------------------------------
// Device globals (allocation-free scratch), 256B-aligned for vector access.
// ---------------------------------------------------------------------------
// gx permuted per consumer block: [dir][blk(64)][t(512)][cl(32)][b(32)]
__device__ __align__(256) float g_gx[2][64][SEQT][32][32];
__device__ __align__(256) float g_hT[2][2][HID][BATCH];   // [parity][dir][unit][batch]
__device__ __align__(256) int   g_arrive[2];              // per-dir step counters

// ---------------------------------------------------------------------------
// Packed fp32x2 FMA (Blackwell FFMA2; only reachable via PTX)
// ---------------------------------------------------------------------------
__device__ __forceinline__ float2 f2fma(float2 a, float2 b, float2 c) {
    unsigned long long ra = *reinterpret_cast<unsigned long long*>(&a);
    unsigned long long rb = *reinterpret_cast<unsigned long long*>(&b);
    unsigned long long rc = *reinterpret_cast<unsigned long long*>(&c);
    unsigned long long rd;
    asm("fma.rn.f32x2 %0, %1, %2, %3;" : "=l"(rd) : "l"(ra), "l"(rb), "l"(rc));
    return *reinterpret_cast<float2*>(&rd);
}
__device__ __forceinline__ float2 f2(float x, float y) { return make_float2(x, y); }

__device__ __forceinline__ float sigf(float x) { return 1.0f / (1.0f + __expf(-x)); }
__device__ __forceinline__ float tanhx(float x) { return 2.0f / (1.0f + __expf(-2.0f * x)) - 1.0f; }

// ---------------------------------------------------------------------------
// Phase 1: gx = x @ W_ih^T + biases (written permuted). Init of h/counters is
// embedded (first 128 blocks also copy h0; block 0 resets counters).
// BM=BN=64, BK=16, 256 thr, 4x4 microtile, dup'd-A f32x2 (R2-proven).
// ---------------------------------------------------------------------------
#define BM 64
#define BN 64
#define BK 16

__global__ __launch_bounds__(256) void gemm_ih_kernel(
        const float* __restrict__ x,
        const float* __restrict__ h0,
        const float* __restrict__ w_f, const float* __restrict__ w_r,
        const float* __restrict__ bi_f, const float* __restrict__ bh_f,
        const float* __restrict__ bi_r, const float* __restrict__ bh_r) {
    const int tid = threadIdx.x;

    // ---- embedded init (h0 -> g_hT[0], counters) ----
    {
        const int gid = (blockIdx.z * gridDim.y + blockIdx.y) * gridDim.x + blockIdx.x;
        if (gid < 128) {
            const int idx = gid * 256 + tid;     // 0..32767
            const int dirI = idx >> 14;
            const int bI = (idx >> 9) & 31;
            const int jI = idx & 511;
            g_hT[0][dirI][jI][bI] = h0[idx];
        }
        if (gid == 0 && tid < 2) g_arrive[tid] = 0;
    }

    const int dir = blockIdx.z;
    const float* __restrict__ w  = dir ? w_r  : w_f;
    const float* __restrict__ bi = dir ? bi_r : bi_f;
    const float* __restrict__ bh = dir ? bh_r : bh_f;

    const int rm0 = blockIdx.y * BM;   // rows over T*B (row = t*32+b)
    const int cn0 = blockIdx.x * BN;   // cols over 4H

    __shared__ __align__(16) float2 Asd[BK][BM + 2];   // A rows, duplicated lanes
    __shared__ __align__(16) float  Ws[BK][BN + 4];

    const int tr = tid / 16;           // 0..15 row group
    const int tc = tid % 16;           // 0..15 col group

    const int l_row = tid >> 2;        // 0..63
    const int l_k4  = (tid & 3) << 2;  // 0,4,8,12

    const int r  = rm0 + l_row;
    int       tt = r >> 5;
    const int bb = r & 31;
    if (dir) tt = (SEQT - 1) - tt;
    const float* a_ptr = x + ((size_t)bb * SEQT + tt) * HID;
    const float* w_ptr = w + (size_t)(cn0 + l_row) * HID;

    float2 acc[4][2];
#pragma unroll
    for (int i = 0; i < 4; i++) { acc[i][0] = f2(0.f, 0.f); acc[i][1] = f2(0.f, 0.f); }

    for (int k0 = 0; k0 < HID; k0 += BK) {
        float4 av = *(const float4*)(a_ptr + k0 + l_k4);
        float4 wv = *(const float4*)(w_ptr + k0 + l_k4);
        __syncthreads();
        Asd[l_k4 + 0][l_row] = f2(av.x, av.x);
        Asd[l_k4 + 1][l_row] = f2(av.y, av.y);
        Asd[l_k4 + 2][l_row] = f2(av.z, av.z);
        Asd[l_k4 + 3][l_row] = f2(av.w, av.w);
        Ws[l_k4 + 0][l_row] = wv.x;
        Ws[l_k4 + 1][l_row] = wv.y;
        Ws[l_k4 + 2][l_row] = wv.z;
        Ws[l_k4 + 3][l_row] = wv.w;
        __syncthreads();
#pragma unroll
        for (int kk = 0; kk < BK; kk++) {
            float4 ad0 = *(const float4*)&Asd[kk][tr * 4];
            float4 ad1 = *(const float4*)&Asd[kk][tr * 4 + 2];
            float4 w4  = *(const float4*)&Ws[kk][tc * 4];
            float2 w01 = f2(w4.x, w4.y);
            float2 w23 = f2(w4.z, w4.w);
            float2 a0 = f2(ad0.x, ad0.y);
            float2 a1 = f2(ad0.z, ad0.w);
            float2 a2 = f2(ad1.x, ad1.y);
            float2 a3 = f2(ad1.z, ad1.w);
            acc[0][0] = f2fma(a0, w01, acc[0][0]); acc[0][1] = f2fma(a0, w23, acc[0][1]);
            acc[1][0] = f2fma(a1, w01, acc[1][0]); acc[1][1] = f2fma(a1, w23, acc[1][1]);
            acc[2][0] = f2fma(a2, w01, acc[2][0]); acc[2][1] = f2fma(a2, w23, acc[2][1]);
            acc[3][0] = f2fma(a3, w01, acc[3][0]); acc[3][1] = f2fma(a3, w23, acc[3][1]);
        }
    }

    // epilogue: write permuted gx. col c -> (blk=(c&511)>>3, cl=(c>>9)*8+(c&7))
    const int cc = cn0 + tc * 4;
    float bsum[4], res[4];
#pragma unroll
    for (int j = 0; j < 4; j++) bsum[j] = bi[cc + j] + bh[cc + j];
#pragma unroll
    for (int i = 0; i < 4; i++) {
        const int rr = rm0 + tr * 4 + i;
        const int t = rr >> 5;
        const int b = rr & 31;
        res[0] = acc[i][0].x + acc[i][0].y * 0.f + acc[i][0].x * 0.f + bsum[0];
        res[0] = acc[i][0].x + bsum[0];
        res[1] = acc[i][0].y + bsum[1];
        res[2] = acc[i][1].x + bsum[2];
        res[3] = acc[i][1].y + bsum[3];
#pragma unroll
        for (int j = 0; j < 4; j++) {
            const int c = cc + j;
            const int blk = (c & 511) >> 3;
            const int cl = (c >> 9) * 8 + (c & 7);
            g_gx[dir][blk][t][cl][b] = res[j];
        }
    }
}

// ---------------------------------------------------------------------------
// Phase 2: persistent recurrence. 128 blocks (64/dir), 256 threads (split-k x2).
// R2-proven layouts: Wd[k][c] dup'd float2, Hs[k][b]. R2 counter sync.
// P row stride 34 (EVEN — odd rows must stay 8B-aligned for float2 access).
// ---------------------------------------------------------------------------
#define NBLK_PER_DIR 64
#define JB 8
#define NC 32
#define PST 34                     // P row stride (floats), must be even
#define PHALF (32 * PST)           // offset of second k-half partials

#define SM_WD 0                    // float2 Wd[512][32] = 131072 B
#define SM_HS 131072               // float  Hs[512][32] =  65536 B
#define SM_P  196608               // float  P[2][32][34]=   8704 B
#define SM_HO 205312               // float  HO[32][8]   =   1024 B
#define SMEM_TOTAL (205312 + 1024)

__global__ __launch_bounds__(256, 1)
void lstm_persistent_kernel(const float* __restrict__ w_hh_f,
                            const float* __restrict__ w_hh_r,
                            const float* __restrict__ c0,
                            float* __restrict__ out) {
    extern __shared__ __align__(16) char smem_raw[];
    float2* Wd = (float2*)(smem_raw + SM_WD);
    float*  Hs = (float*)(smem_raw + SM_HS);
    float*  P  = (float*)(smem_raw + SM_P);    // [ks][c][b], row stride PST
    float*  HO = (float*)(smem_raw + SM_HO);   // [b][8]

    const int tid = threadIdx.x;
    const int dir = blockIdx.x >> 6;
    const int blk = blockIdx.x & 63;
    const int j0  = blk * JB;
    const float* __restrict__ w = dir ? w_hh_r : w_hh_f;
    int* arrive = &g_arrive[dir];

    // ---- load + duplicate W slice (once): Wd[k][c] ----
    {
        const int c   = tid >> 3;              // 0..31 local gate col
        const int seg = tid & 7;               // k segment of 64
        const int g = c >> 3, u = c & 7;
        const float* wrow = w + (size_t)(g * HID + j0 + u) * HID + seg * 64;
#pragma unroll
        for (int q = 0; q < 16; q++) {
            float4 v = *(const float4*)(wrow + q * 4);
            const int k = seg * 64 + q * 4;
            Wd[(k + 0) * NC + c] = f2(v.x, v.x);
            Wd[(k + 1) * NC + c] = f2(v.y, v.y);
            Wd[(k + 2) * NC + c] = f2(v.z, v.z);
            Wd[(k + 3) * NC + c] = f2(v.w, v.w);
        }
    }

    // ---- pointwise ownership: thread -> (u = tid>>5, b = tid&31) ----
    const int pu = tid >> 5;
    const int pb = tid & 31;
    float creg = c0[((size_t)dir * BATCH + pb) * HID + j0 + pu];

    // ---- GEMM coords: ks = k-half, 8 batch-groups x 16 col-groups ----
    const int ks  = tid >> 7;                  // 0/1
    const int t7  = tid & 127;
    const int bg  = t7 & 7;
    const int cg  = t7 >> 3;
    const int b0  = bg * 4;
    const int cl0 = cg * 2;
    const int k0s = ks * 256;
    float* Pp = P + ks * PHALF;

    const float4* hT4b0 = (const float4*)&g_hT[0][dir][0][0];
    const float4* hT4b1 = (const float4*)&g_hT[1][dir][0][0];
    float4* Hs4 = (float4*)Hs;
    const float* gxbase = &g_gx[dir][blk][0][0][0];

    __syncthreads();

    for (int t = 0; t < SEQT; t++) {
        // prefetch gx (coalesced; in flight during the wait). ks=0 only uses it.
        const float* gxp = gxbase + (size_t)t * 1024;
        float4 gxa = *(const float4*)(gxp + cl0 * 32 + b0);
        float4 gxb = *(const float4*)(gxp + (cl0 + 1) * 32 + b0);

        // wait for all same-dir blocks to finish step t-1 (R2 counter scheme)
        if (t > 0 && tid == 0) {
            const int target = NBLK_PER_DIR * t;
            int v;
            do {
                asm volatile("ld.acquire.gpu.s32 %0, [%1];" : "=r"(v) : "l"(arrive));
            } while (v < target);
        }
        __syncthreads();

        // stage h (64KB) into Hs[k][b], straight coalesced copy
        const float4* src = (t & 1) ? hT4b1 : hT4b0;
#pragma unroll
        for (int it = 0; it < 16; it++) Hs4[it * 256 + tid] = src[it * 256 + tid];
        __syncthreads();

        // GEMM half: C[b][c] += sum_{k in half} h[b][k]*W[c][k]; lanes = batch pairs
        float2 a00 = f2(0.f, 0.f), a01 = f2(0.f, 0.f);
        float2 a10 = f2(0.f, 0.f), a11 = f2(0.f, 0.f);
#pragma unroll 8
        for (int k = 0; k < 256; k++) {
            const int kk = k0s + k;
            float4 h4 = *(const float4*)&Hs[kk * NC + b0];
            float4 wv = *(const float4*)&Wd[kk * NC + cl0];
            float2 h01 = f2(h4.x, h4.y);
            float2 h23 = f2(h4.z, h4.w);
            float2 w0d = f2(wv.x, wv.y);
            float2 w1d = f2(wv.z, wv.w);
            a00 = f2fma(h01, w0d, a00);
            a01 = f2fma(h01, w1d, a01);
            a10 = f2fma(h23, w0d, a10);
            a11 = f2fma(h23, w1d, a11);
        }
        if (ks == 0) {       // fold gx into the ks=0 partial
            a00.x += gxa.x; a00.y += gxa.y;
            a01.x += gxb.x; a01.y += gxb.y;
            a10.x += gxa.z; a10.y += gxa.w;
            a11.x += gxb.z; a11.y += gxb.w;
        }
        *(float2*)&Pp[(cl0)     * PST + b0]     = a00;
        *(float2*)&Pp[(cl0 + 1) * PST + b0]     = a01;
        *(float2*)&Pp[(cl0)     * PST + b0 + 2] = a10;
        *(float2*)&Pp[(cl0 + 1) * PST + b0 + 2] = a11;
        __syncthreads();

        // pointwise: 1 item/thread; sum the two k-half partials
        float* hdst = (t & 1) ? (float*)&g_hT[0][dir][0][0]
                              : (float*)&g_hT[1][dir][0][0];
        {
            const float pi = P[(pu)      * PST + pb] + P[PHALF + (pu)      * PST + pb];
            const float pf = P[(8 + pu)  * PST + pb] + P[PHALF + (8 + pu)  * PST + pb];
            const float pg = P[(16 + pu) * PST + pb] + P[PHALF + (16 + pu) * PST + pb];
            const float po = P[(24 + pu) * PST + pb] + P[PHALF + (24 + pu) * PST + pb];
            const float iv = sigf(pi);
            const float fv = sigf(pf);
            const float gv = tanhx(pg);
            const float ov = sigf(po);
            creg = fv * creg + iv * gv;
            const float hnew = ov * tanhx(creg);
            hdst[(j0 + pu) * BATCH + pb] = hnew;     // coalesced per warp
            HO[pb * 8 + pu] = hnew;
            if (t == SEQT - 1) {
                out[OUT_HN + ((size_t)dir * BATCH + pb) * HID + j0 + pu] = hnew;
                out[OUT_CN + ((size_t)dir * BATCH + pb) * HID + j0 + pu] = creg;
            }
        }
        __syncthreads();   // hdst + HO visible

        // coalesced out write (128 threads x float2)
        if (tid < 128) {
            const int tout = dir ? (SEQT - 1 - t) : t;
            const int ob = tid >> 2;
            const int ou = (tid & 3) * 2;
            float2 v = *(const float2*)&HO[ob * 8 + ou];
            *(float2*)&out[((size_t)ob * SEQT + tout) * (2 * HID) + dir * HID + j0 + ou] = v;
        }

        // signal completion of step t
        if (tid == 0) {
            int dummy;
            asm volatile("atom.release.gpu.add.s32 %0, [%1], 1;"
                         : "=r"(dummy) : "l"(arrive));
        }
    }
}

// ---------------------------------------------------------------------------
// Launch
// ---------------------------------------------------------------------------
extern "C" void kernel_launch(void* const* d_in, const int* in_sizes, int n_in,
                              void* d_out, int out_size) {
    const float* x      = (const float*)d_in[0];
    const float* h0     = (const float*)d_in[1];
    const float* c0     = (const float*)d_in[2];
    const float* w_ih_f = (const float*)d_in[3];
    const float* w_hh_f = (const float*)d_in[4];
    const float* b_ih_f = (const float*)d_in[5];
    const float* b_hh_f = (const float*)d_in[6];
    const float* w_ih_r = (const float*)d_in[7];
    const float* w_hh_r = (const float*)d_in[8];
    const float* b_ih_r = (const float*)d_in[9];
    const float* b_hh_r = (const float*)d_in[10];
    float* out = (float*)d_out;

    cudaFuncSetAttribute(lstm_persistent_kernel,
                         cudaFuncAttributeMaxDynamicSharedMemorySize, SMEM_TOTAL);

    dim3 ggrid(G4 / BN, (SEQT * BATCH) / BM, 2);   // (32, 256, 2)
    gemm_ih_kernel<<<ggrid, 256>>>(x, h0, w_ih_f, w_ih_r,
                                   b_ih_f, b_hh_f, b_ih_r, b_hh_r);

    lstm_persistent_kernel<<<2 * NBLK_PER_DIR, 256, SMEM_TOTAL>>>(
        w_hh_f, w_hh_r, c0, out);
}